// round 1
// baseline (speedup 1.0000x reference)
#include <cuda_runtime.h>

#define NB 256   // batch
#define ND 16    // manifold dim
#define NH 128   // hidden
#define R2H 256  // 2H

// ---- scratch (device globals; no allocation) ----
__device__ float g_metric[NB * 256];          // metric[b][i*16+j]
__device__ float g_PB[NB * 256];              // points@rW1[0:16] + rb1
__device__ float g_M1[NB * ND * 256];         // metric[b,i,:]@rW1[16:32]
__device__ float g_M2[NB * ND * 256];         // metric[b,j,:]@rW1[32:48]
__device__ float g_Spart[NB * ND * 256];      // per-(b,i) partial hidden sums

// accurate fast tanh: 1 - 2/(exp(2x)+1); abs err ~1e-7 (ex2.approx + rcp.approx)
__device__ __forceinline__ float fast_tanh(float x) {
    float e = __expf(2.0f * x);                 // MUFU ex2
    return 1.0f - __fdividef(2.0f, e + 1.0f);   // MUFU rcp + mul
}

// ============================================================================
// K1: metric + precomputed ricci-layer1 terms (per-b block, 256 threads)
// ============================================================================
__global__ __launch_bounds__(256) void k_metric(
    const float* __restrict__ points,
    const float* __restrict__ mW1, const float* __restrict__ mb1,
    const float* __restrict__ mW2, const float* __restrict__ mb2,
    const float* __restrict__ rW1, const float* __restrict__ rb1)
{
    int b = blockIdx.x;
    int t = threadIdx.x;
    __shared__ float pts[ND];
    __shared__ float mh[NH];
    __shared__ float mraw[256];
    __shared__ float met[256];
    __shared__ float rw1m[32 * 256];   // rW1 rows 16..47

    if (t < ND) pts[t] = points[b * ND + t];
    #pragma unroll
    for (int r = 0; r < 32; r++) rw1m[r * 256 + t] = rW1[(16 + r) * 256 + t];
    __syncthreads();

    if (t < NH) {
        float a = mb1[t];
        #pragma unroll
        for (int p = 0; p < ND; p++) a = fmaf(pts[p], mW1[p * NH + t], a);
        mh[t] = fmaxf(a, 0.0f);
    }
    __syncthreads();

    {
        float a = mb2[t];
        #pragma unroll 8
        for (int h = 0; h < NH; h++) a = fmaf(mh[h], mW2[h * 256 + t], a);
        mraw[t] = a;
    }
    __syncthreads();

    {
        int i = t >> 4, j = t & 15;
        float m = 0.5f * (mraw[i * 16 + j] + mraw[j * 16 + i]) + (i == j ? 1e-6f : 0.0f);
        met[t] = m;
        g_metric[b * 256 + t] = m;
    }

    // PB[b][o] = rb1[o] + sum_p points[p]*rW1[p][o]
    {
        float a = rb1[t];
        #pragma unroll
        for (int p = 0; p < ND; p++) a = fmaf(pts[p], rW1[p * 256 + t], a);
        g_PB[b * 256 + t] = a;
    }
    __syncthreads();

    // M1[b][i][o], M2[b][i][o]
    for (int i = 0; i < ND; i++) {
        float a1 = 0.0f, a2 = 0.0f;
        #pragma unroll
        for (int p = 0; p < ND; p++) {
            float mv = met[i * 16 + p];
            a1 = fmaf(mv, rw1m[p * 256 + t], a1);
            a2 = fmaf(mv, rw1m[(16 + p) * 256 + t], a2);
        }
        g_M1[(b * ND + i) * 256 + t] = a1;
        g_M2[(b * ND + i) * 256 + t] = a2;
    }
}

// ============================================================================
// K2: main fused kernel. One block per (i, b); 256 threads.
//   Stage A: thread (j,k) computes christoffel[b,i,j,k]  (128h tanh MLP)
//   Stage B: thread o accumulates relu hidden sums over j into g_Spart[b,i,o]
// ============================================================================
__global__ __launch_bounds__(256) void k_main(
    const float* __restrict__ cW1, const float* __restrict__ cb1,
    const float* __restrict__ cW2, const float* __restrict__ cb2,
    const float* __restrict__ rW1)
{
    int i = blockIdx.x;   // 0..15
    int b = blockIdx.y;   // 0..255
    int t = threadIdx.x;  // 0..255

    __shared__ float met[256];
    __shared__ float4 cw[NH];      // (w0, w1, w2, cb1)
    __shared__ float  cw2s[NH];
    __shared__ __align__(16) float chs[256];

    met[t] = g_metric[b * 256 + t];
    if (t < NH) {
        cw[t] = make_float4(cW1[t], cW1[NH + t], cW1[2 * NH + t], cb1[t]);
        cw2s[t] = cW2[t];
    }
    __syncthreads();

    // ---- Stage A: christoffel for (i, j=t>>4, k=t&15) ----
    {
        int j = t >> 4, k = t & 15;
        float mij = met[i * 16 + j];
        float mjk = met[j * 16 + k];
        float mki = met[i * 16 + k];   // metric symmetric: m[k][i] == m[i][k]
        float acc0 = cb2[0], acc1 = 0.0f;
        #pragma unroll 4
        for (int h = 0; h < NH; h += 2) {
            float4 w = cw[h];
            float x = fmaf(mki, w.z, fmaf(mjk, w.y, fmaf(mij, w.x, w.w)));
            acc0 = fmaf(cw2s[h], fast_tanh(x), acc0);
            float4 w2 = cw[h + 1];
            float x2 = fmaf(mki, w2.z, fmaf(mjk, w2.y, fmaf(mij, w2.x, w2.w)));
            acc1 = fmaf(cw2s[h + 1], fast_tanh(x2), acc1);
        }
        chs[t] = acc0 + acc1;
    }
    __syncthreads();

    // ---- Stage B: hidden layer of ricci net, reduced over j ----
    {
        int o = t;
        const float* rW1c = rW1 + 48 * 256;
        float rw[ND];
        #pragma unroll
        for (int k = 0; k < ND; k++) rw[k] = rW1c[k * 256 + o];

        float pm = g_PB[b * 256 + o] + g_M1[(b * ND + i) * 256 + o];
        float s = 0.0f;
        #pragma unroll 4
        for (int j = 0; j < ND; j++) {
            float a = pm + g_M2[(b * ND + j) * 256 + o];
            const float4* chr = (const float4*)&chs[j * 16];
            #pragma unroll
            for (int q = 0; q < 4; q++) {
                float4 c = chr[q];
                a = fmaf(c.x, rw[4 * q + 0], a);
                a = fmaf(c.y, rw[4 * q + 1], a);
                a = fmaf(c.z, rw[4 * q + 2], a);
                a = fmaf(c.w, rw[4 * q + 3], a);
            }
            s += fmaxf(a, 0.0f);
        }
        g_Spart[(b * ND + i) * 256 + o] = s;   // deterministic partials, no atomics
    }
}

// ============================================================================
// K3: reduce partials, tiny output GEMM, symmetrize
//   ricci[b] = sym( (S[b]/256) @ rW2 + rb2 )
// ============================================================================
__global__ __launch_bounds__(256) void k_final(
    const float* __restrict__ rW2, const float* __restrict__ rb2,
    float* __restrict__ out)
{
    int b = blockIdx.x;
    int t = threadIdx.x;
    __shared__ float Ss[256];
    __shared__ float raw[256];

    float s = 0.0f;
    #pragma unroll
    for (int i = 0; i < ND; i++) s += g_Spart[(b * ND + i) * 256 + t];
    Ss[t] = s * (1.0f / 256.0f);
    __syncthreads();

    float a = rb2[t];
    #pragma unroll 8
    for (int h = 0; h < R2H; h++) a = fmaf(Ss[h], rW2[h * 256 + t], a);
    raw[t] = a;
    __syncthreads();

    int i = t >> 4, j = t & 15;
    out[b * 256 + t] = 0.5f * (raw[i * 16 + j] + raw[j * 16 + i]);
}

// ============================================================================
extern "C" void kernel_launch(void* const* d_in, const int* in_sizes, int n_in,
                              void* d_out, int out_size)
{
    const float* points = (const float*)d_in[0];
    const float* mW1    = (const float*)d_in[1];
    const float* mb1    = (const float*)d_in[2];
    const float* mW2    = (const float*)d_in[3];
    const float* mb2    = (const float*)d_in[4];
    const float* cW1    = (const float*)d_in[5];
    const float* cb1    = (const float*)d_in[6];
    const float* cW2    = (const float*)d_in[7];
    const float* cb2    = (const float*)d_in[8];
    const float* rW1    = (const float*)d_in[9];
    const float* rb1    = (const float*)d_in[10];
    const float* rW2    = (const float*)d_in[11];
    const float* rb2    = (const float*)d_in[12];
    float* out = (float*)d_out;

    k_metric<<<NB, 256>>>(points, mW1, mb1, mW2, mb2, rW1, rb1);
    dim3 grid2(ND, NB);
    k_main<<<grid2, 256>>>(cW1, cb1, cW2, cb2, rW1);
    k_final<<<NB, 256>>>(rW2, rb2, out);
}

// round 2
// speedup vs baseline: 1.2929x; 1.2929x over previous
#include <cuda_runtime.h>
#include <cstdint>

#define NB 256   // batch
#define ND 16    // manifold dim
#define NH 128   // hidden
#define R2H 256  // 2H

// ---- scratch (device globals; no allocation) ----
__device__ float g_metric[NB * 256];          // metric[b][i*16+j]
__device__ float g_PB[NB * 256];              // points@rW1[0:16] + rb1
__device__ float g_M1[NB * ND * 256];         // metric[b,i,:]@rW1[16:32]
__device__ float g_M2[NB * ND * 256];         // metric[b,j,:]@rW1[32:48]
__device__ float g_Spart[NB * ND * 256];      // per-(b,i) partial hidden sums

// single-MUFU tanh
__device__ __forceinline__ float tanh_fast(float x) {
    float y;
    asm("tanh.approx.f32 %0, %1;" : "=f"(y) : "f"(x));
    return y;
}

// packed f32x2 helpers
__device__ __forceinline__ uint64_t pk2(float lo, float hi) {
    uint64_t r; asm("mov.b64 %0, {%1, %2};" : "=l"(r) : "f"(lo), "f"(hi)); return r;
}
__device__ __forceinline__ uint64_t fma2(uint64_t a, uint64_t b, uint64_t c) {
    uint64_t d; asm("fma.rn.f32x2 %0, %1, %2, %3;" : "=l"(d) : "l"(a), "l"(b), "l"(c)); return d;
}
__device__ __forceinline__ void unpk2(uint64_t v, float& lo, float& hi) {
    asm("mov.b64 {%0, %1}, %2;" : "=f"(lo), "=f"(hi) : "l"(v));
}

// ============================================================================
// K1: metric + precomputed ricci-layer1 terms (per-b block, 256 threads)
//     rW1 columns held in registers (no big smem -> high occupancy)
// ============================================================================
__global__ __launch_bounds__(256) void k_metric(
    const float* __restrict__ points,
    const float* __restrict__ mW1, const float* __restrict__ mb1,
    const float* __restrict__ mW2, const float* __restrict__ mb2,
    const float* __restrict__ rW1, const float* __restrict__ rb1)
{
    int b = blockIdx.x;
    int t = threadIdx.x;
    __shared__ float pts[ND];
    __shared__ float mh[NH];
    __shared__ float mraw[256];
    __shared__ float met[256];

    // per-thread register copy of rW1 rows 16..47, column t (coalesced loads)
    float rwA[ND], rwB[ND];
    #pragma unroll
    for (int p = 0; p < ND; p++) {
        rwA[p] = rW1[(16 + p) * 256 + t];
        rwB[p] = rW1[(32 + p) * 256 + t];
    }

    if (t < ND) pts[t] = points[b * ND + t];
    __syncthreads();

    if (t < NH) {
        float a = mb1[t];
        #pragma unroll
        for (int p = 0; p < ND; p++) a = fmaf(pts[p], mW1[p * NH + t], a);
        mh[t] = fmaxf(a, 0.0f);
    }
    __syncthreads();

    {
        float a = mb2[t];
        #pragma unroll 8
        for (int h = 0; h < NH; h++) a = fmaf(mh[h], mW2[h * 256 + t], a);
        mraw[t] = a;
    }
    __syncthreads();

    {
        int i = t >> 4, j = t & 15;
        float m = 0.5f * (mraw[i * 16 + j] + mraw[j * 16 + i]) + (i == j ? 1e-6f : 0.0f);
        met[t] = m;
        g_metric[b * 256 + t] = m;
    }

    // PB[b][o] = rb1[o] + sum_p points[p]*rW1[p][o]
    {
        float a = rb1[t];
        #pragma unroll
        for (int p = 0; p < ND; p++) a = fmaf(pts[p], rW1[p * 256 + t], a);
        g_PB[b * 256 + t] = a;
    }
    __syncthreads();

    // M1[b][i][o], M2[b][i][o] from registers + broadcast smem
    #pragma unroll
    for (int i = 0; i < ND; i++) {
        float a1 = 0.0f, a2 = 0.0f;
        #pragma unroll
        for (int p = 0; p < ND; p++) {
            float mv = met[i * 16 + p];
            a1 = fmaf(mv, rwA[p], a1);
            a2 = fmaf(mv, rwB[p], a2);
        }
        g_M1[(b * ND + i) * 256 + t] = a1;
        g_M2[(b * ND + i) * 256 + t] = a2;
    }
}

// ============================================================================
// K2: main fused kernel. One block per (i, b); 256 threads.
//   Stage A: thread (j,k) computes christoffel[b,i,j,k] via packed-FMA MLP
//            with single-MUFU tanh.approx
//   Stage B: thread o accumulates relu hidden sums over j into g_Spart[b,i,o]
// ============================================================================
__global__ __launch_bounds__(256) void k_main(
    const float* __restrict__ cW1, const float* __restrict__ cb1,
    const float* __restrict__ cW2, const float* __restrict__ cb2,
    const float* __restrict__ rW1)
{
    int i = blockIdx.x;   // 0..15
    int b = blockIdx.y;   // 0..255
    int t = threadIdx.x;  // 0..255

    __shared__ float met[256];
    // packed weight pairs (h=2q, h=2q+1)
    __shared__ float2 w0p[NH / 2], w1p[NH / 2], w2p[NH / 2], wbp[NH / 2], v2p[NH / 2];
    __shared__ __align__(16) float chs[256];

    met[t] = g_metric[b * 256 + t];
    if (t < NH / 2) {
        const float2* c0 = (const float2*)cW1;            // row 0
        const float2* c1 = (const float2*)(cW1 + NH);     // row 1
        const float2* c2 = (const float2*)(cW1 + 2 * NH); // row 2
        const float2* cb = (const float2*)cb1;
        const float2* v2 = (const float2*)cW2;
        w0p[t] = c0[t]; w1p[t] = c1[t]; w2p[t] = c2[t];
        wbp[t] = cb[t]; v2p[t] = v2[t];
    }
    __syncthreads();

    // ---- Stage A: christoffel for (i, j=t>>4, k=t&15) ----
    {
        int j = t >> 4, k = t & 15;
        float mij = met[i * 16 + j];
        float mjk = met[j * 16 + k];
        float mki = met[i * 16 + k];   // metric symmetric
        uint64_t mij2 = pk2(mij, mij);
        uint64_t mjk2 = pk2(mjk, mjk);
        uint64_t mki2 = pk2(mki, mki);

        float acc0 = cb2[0], acc1 = 0.0f;
        #pragma unroll 8
        for (int q = 0; q < NH / 2; q++) {
            float2 w0 = w0p[q], w1 = w1p[q], w2 = w2p[q], wb = wbp[q], v2 = v2p[q];
            uint64_t x = fma2(mij2, pk2(w0.x, w0.y), pk2(wb.x, wb.y));
            x = fma2(mjk2, pk2(w1.x, w1.y), x);
            x = fma2(mki2, pk2(w2.x, w2.y), x);
            float xa, xb; unpk2(x, xa, xb);
            acc0 = fmaf(v2.x, tanh_fast(xa), acc0);
            acc1 = fmaf(v2.y, tanh_fast(xb), acc1);
        }
        chs[t] = acc0 + acc1;
    }
    __syncthreads();

    // ---- Stage B: hidden layer of ricci net, reduced over j ----
    {
        int o = t;
        const float* rW1c = rW1 + 48 * 256;
        float rw[ND];
        #pragma unroll
        for (int k = 0; k < ND; k++) rw[k] = rW1c[k * 256 + o];

        float pm = g_PB[b * 256 + o] + g_M1[(b * ND + i) * 256 + o];
        float s = 0.0f;
        #pragma unroll 4
        for (int j = 0; j < ND; j++) {
            float a = pm + g_M2[(b * ND + j) * 256 + o];
            const float4* chr = (const float4*)&chs[j * 16];
            #pragma unroll
            for (int q = 0; q < 4; q++) {
                float4 c = chr[q];
                a = fmaf(c.x, rw[4 * q + 0], a);
                a = fmaf(c.y, rw[4 * q + 1], a);
                a = fmaf(c.z, rw[4 * q + 2], a);
                a = fmaf(c.w, rw[4 * q + 3], a);
            }
            s += fmaxf(a, 0.0f);
        }
        g_Spart[(b * ND + i) * 256 + o] = s;   // deterministic partials, no atomics
    }
}

// ============================================================================
// K3: reduce partials, tiny output GEMM, symmetrize
//   ricci[b] = sym( (S[b]/256) @ rW2 + rb2 )
// ============================================================================
__global__ __launch_bounds__(256) void k_final(
    const float* __restrict__ rW2, const float* __restrict__ rb2,
    float* __restrict__ out)
{
    int b = blockIdx.x;
    int t = threadIdx.x;
    __shared__ float Ss[256];
    __shared__ float raw[256];

    float s = 0.0f;
    #pragma unroll
    for (int i = 0; i < ND; i++) s += g_Spart[(b * ND + i) * 256 + t];
    Ss[t] = s * (1.0f / 256.0f);
    __syncthreads();

    float a = rb2[t];
    #pragma unroll 8
    for (int h = 0; h < R2H; h++) a = fmaf(Ss[h], rW2[h * 256 + t], a);
    raw[t] = a;
    __syncthreads();

    int i = t >> 4, j = t & 15;
    out[b * 256 + t] = 0.5f * (raw[i * 16 + j] + raw[j * 16 + i]);
}

// ============================================================================
extern "C" void kernel_launch(void* const* d_in, const int* in_sizes, int n_in,
                              void* d_out, int out_size)
{
    const float* points = (const float*)d_in[0];
    const float* mW1    = (const float*)d_in[1];
    const float* mb1    = (const float*)d_in[2];
    const float* mW2    = (const float*)d_in[3];
    const float* mb2    = (const float*)d_in[4];
    const float* cW1    = (const float*)d_in[5];
    const float* cb1    = (const float*)d_in[6];
    const float* cW2    = (const float*)d_in[7];
    const float* cb2    = (const float*)d_in[8];
    const float* rW1    = (const float*)d_in[9];
    const float* rb1    = (const float*)d_in[10];
    const float* rW2    = (const float*)d_in[11];
    const float* rb2    = (const float*)d_in[12];
    float* out = (float*)d_out;

    k_metric<<<NB, 256>>>(points, mW1, mb1, mW2, mb2, rW1, rb1);
    dim3 grid2(ND, NB);
    k_main<<<grid2, 256>>>(cW1, cb1, cW2, cb2, rW1);
    k_final<<<NB, 256>>>(rW2, rb2, out);
}